// round 17
// baseline (speedup 1.0000x reference)
#include <cuda_runtime.h>
#include <cstdint>

#define D_MODEL    1024
#define N_LEVELS   8
#define TPB        512               // 16 warps = 8 pairs; pair owns 32 rows
#define NWARP      16
#define CHUNK_COLS 16
#define CHUNKS_PER_WARP 32           // 512 cols / 16
#define NBUF       4
#define ROW_STRIDE_F 20              // 16 + 4 pad words -> conflict-free LDS.128 phases
#define ROW_STRIDE_B (ROW_STRIDE_F * 4)          // 80 B
#define CHUNK_BUF_B (32 * ROW_STRIDE_B)          // 2560 B (32 rows x 16 cols)
#define HALF_L 3.9960f
#define LN_EPS 1e-5f
#define INV_D  (1.0f / 1024.0f)

// dynamic smem layout
#define OFF_BUFS 0                                    // 16 x 4 x 2560 = 163840
#define OFF_GW   (NWARP * NBUF * CHUNK_BUF_B)         // 163840: longlong2 gw[256][8] = 32768
#define OFF_CV   (OFF_GW + 256 * 8 * 16)              // 196608: float G[8], C[8]
#define OFF_TMP  (OFF_CV + 64)                        // 196672: float tmp[16][16] = 1024
#define OFF_PB   (OFF_TMP + 1024)                     // 197696: float pb[8][32][10] = 10240
#define SMEM_TOTAL (OFF_PB + 10240)                   // 207936 B (<= 227KB carveout)

typedef unsigned long long ull;

__device__ __forceinline__ ull pack2(float lo, float hi) {
    ull r; asm("mov.b64 %0, {%1, %2};" : "=l"(r) : "f"(lo), "f"(hi)); return r;
}
__device__ __forceinline__ void unpack2(ull p, float& lo, float& hi) {
    asm("mov.b64 {%0, %1}, %2;" : "=f"(lo), "=f"(hi) : "l"(p));
}
__device__ __forceinline__ ull fma2(ull a, ull b, ull c) {
    ull d; asm("fma.rn.f32x2 %0, %1, %2, %3;" : "=l"(d) : "l"(a), "l"(b), "l"(c)); return d;
}
__device__ __forceinline__ ull add2(ull a, ull b) {
    ull d; asm("add.rn.f32x2 %0, %1, %2;" : "=l"(d) : "l"(a), "l"(b)); return d;
}
__device__ __forceinline__ void cp16(uint32_t dst, const float* src) {
    asm volatile("cp.async.cg.shared.global [%0], [%1], 16;" :: "r"(dst), "l"(src));
}

__global__ __launch_bounds__(TPB, 1) void fsq_kernel(
    const float* __restrict__ x,     // [rows, 1024]
    const float* __restrict__ ln_w,  // [1024]
    const float* __restrict__ ln_b,  // [1024]
    const float* __restrict__ W,     // [8, 1024]
    float* __restrict__ out,         // [rows, 8]
    int rows)
{
    extern __shared__ char smem[];
    longlong2* gw    = (longlong2*)(smem + OFF_GW);   // [quad 0..255][level 0..7], 16B each
    float* sG        = (float*)(smem + OFF_CV);
    float* sC        = (float*)(smem + OFF_CV) + 8;
    float (*tmp)[16] = (float(*)[16])(smem + OFF_TMP);
    float (*pb)[32][10] = (float(*)[32][10])(smem + OFF_PB);

    const int t = threadIdx.x;          // 0..511
    const int w = t >> 5, L = t & 31;

    // ===== preamble pass 1: G_n = sum(ln_w*W[n]), C_n = sum(ln_b*W[n]) =====
    {
        float v[16];
        #pragma unroll
        for (int k = 0; k < 16; k++) v[k] = 0.f;
        if (t < 256) {                                // quad t
            float lw4[4], lb4[4];
            #pragma unroll
            for (int j = 0; j < 4; j++) { lw4[j] = ln_w[4*t + j]; lb4[j] = ln_b[4*t + j]; }
            #pragma unroll
            for (int n = 0; n < N_LEVELS; n++) {
                #pragma unroll
                for (int j = 0; j < 4; j++) {
                    float wv = W[n * D_MODEL + 4*t + j];
                    v[n]     = fmaf(lw4[j], wv, v[n]);
                    v[8 + n] = fmaf(lb4[j], wv, v[8 + n]);
                }
            }
        }
        #pragma unroll
        for (int off = 16; off > 0; off >>= 1)
            #pragma unroll
            for (int k = 0; k < 16; k++)
                v[k] += __shfl_xor_sync(0xFFFFFFFFu, v[k], off);
        if (L == 0)
            #pragma unroll
            for (int k = 0; k < 16; k++) tmp[w][k] = v[k];
        __syncthreads();
        if (t < 16) {
            float s = 0.f;
            #pragma unroll
            for (int ww = 0; ww < NWARP; ww++) s += tmp[ww][t];
            if (t < 8) sG[t] = s; else sC[t - 8] = s;
        }
        __syncthreads();
    }
    // ===== preamble pass 2: centered g'[n][d] = ln_w[d]*W[n][d] - G_n/D =====
    if (t < 256) {
        float lw4[4];
        #pragma unroll
        for (int j = 0; j < 4; j++) lw4[j] = ln_w[4*t + j];
        #pragma unroll
        for (int n = 0; n < N_LEVELS; n++) {
            float gn = sG[n] * INV_D;
            float g0 = fmaf(lw4[0], W[n * D_MODEL + 4*t + 0], -gn);
            float g1 = fmaf(lw4[1], W[n * D_MODEL + 4*t + 1], -gn);
            float g2 = fmaf(lw4[2], W[n * D_MODEL + 4*t + 2], -gn);
            float g3 = fmaf(lw4[3], W[n * D_MODEL + 4*t + 3], -gn);
            longlong2 p;
            p.x = (long long)pack2(g0, g1);
            p.y = (long long)pack2(g2, g3);
            gw[t * 8 + n] = p;
        }
    }
    __syncthreads();   // gw visible; last block-wide barrier

    // ===== mainloop: pair (w>>1) owns 32 rows; warp parity (w&1) owns a 512-col half =====
    const int pairid = w >> 1;
    const int p      = w & 1;
    const size_t rowbase = (size_t)blockIdx.x * 256 + (size_t)pairid * 32;
    const uint32_t smem_u = (uint32_t)__cvta_generic_to_shared(smem);
    const uint32_t mybufs = smem_u + OFF_BUFS + w * NBUF * CHUNK_BUF_B;

    // loader: lane covers quad (L&3) of rows (L>>2)+8u, u=0..3
    const int qd = L & 3;
    const int rb = L >> 2;
    size_t gr0 = rowbase + rb;
    if (gr0 >= (size_t)rows) gr0 = rows - 1;           // clamp, never OOB
    const float* src0 = x + gr0 * D_MODEL + p * 512 + qd * 4;
    const uint32_t dst0 = mybufs + rb * ROW_STRIDE_B + qd * 16;

    auto issue = [&](int chunk, int b) {
        const float* s0 = src0 + chunk * CHUNK_COLS;
        uint32_t d0 = dst0 + b * CHUNK_BUF_B;
        #pragma unroll
        for (int u = 0; u < 4; u++)
            cp16(d0 + u * 8 * ROW_STRIDE_B, s0 + (size_t)u * 8 * D_MODEL);
    };

    #pragma unroll
    for (int c = 0; c < NBUF; c++) {
        issue(c, c);
        asm volatile("cp.async.commit_group;" ::: "memory");
    }

    ull s2 = 0, q2 = 0, d2[N_LEVELS];
    #pragma unroll
    for (int n = 0; n < N_LEVELS; n++) d2[n] = 0;

    const char* lrow = smem + OFF_BUFS + (size_t)w * NBUF * CHUNK_BUF_B
                     + (size_t)L * ROW_STRIDE_B;

    for (int c = 0; c < CHUNKS_PER_WARP; c++) {
        asm volatile("cp.async.wait_group 3;" ::: "memory");
        __syncwarp();

        const longlong2* trow = (const longlong2*)(lrow + (c & 3) * CHUNK_BUF_B);
        // warp's first quad of this chunk = p*128 + c*4 (uniform across lanes)
        const longlong2* gq = gw + ((p * 128 + c * 4) * 8);
        #pragma unroll
        for (int j = 0; j < 4; j++) {
            longlong2 xv = trow[j];
            ull a = (ull)xv.x, bb = (ull)xv.y;
            s2 = add2(s2, add2(a, bb));
            q2 = fma2(a, a, q2);
            q2 = fma2(bb, bb, q2);
            #pragma unroll
            for (int n = 0; n < N_LEVELS; n++) {
                longlong2 g = gq[j * 8 + n];          // full-warp broadcast LDS
                d2[n] = fma2(a,  (ull)g.x, d2[n]);
                d2[n] = fma2(bb, (ull)g.y, d2[n]);
            }
        }
        __syncwarp();                                 // lanes done with buf c&3
        if (c + NBUF < CHUNKS_PER_WARP) issue(c + NBUF, c & 3);
        asm volatile("cp.async.commit_group;" ::: "memory");  // uniform group count
    }

    // ===== epilogue: combine the warp pair via smem + named barrier =====
    float v[10];
    {
        float lo, hi;
        unpack2(s2, lo, hi); v[0] = lo + hi;
        unpack2(q2, lo, hi); v[1] = lo + hi;
        #pragma unroll
        for (int n = 0; n < N_LEVELS; n++) { unpack2(d2[n], lo, hi); v[2 + n] = lo + hi; }
    }

    if (p == 1) {
        #pragma unroll
        for (int k = 0; k < 10; k++) pb[pairid][L][k] = v[k];
    }
    // named barrier per pair (IDs 8..15 to stay clear of barrier 0)
    asm volatile("bar.sync %0, 64;" :: "r"(pairid + 8) : "memory");

    if (p == 0) {
        #pragma unroll
        for (int k = 0; k < 10; k++) v[k] += pb[pairid][L][k];

        size_t grow = rowbase + L;
        if (grow < (size_t)rows) {
            float mean = v[0] * INV_D;
            float var  = fmaf(v[1], INV_D, -mean * mean);
            float rstd = rsqrtf(var + LN_EPS);
            float o[N_LEVELS];
            #pragma unroll
            for (int n = 0; n < N_LEVELS; n++) {
                float z = fmaf(rstd, v[2 + n], sC[n]);   // mean folded into centered g'
                o[n] = rintf(HALF_L * tanhf(z));
            }
            float4* op = (float4*)(out + grow * N_LEVELS);
            op[0] = make_float4(o[0], o[1], o[2], o[3]);
            op[1] = make_float4(o[4], o[5], o[6], o[7]);
        }
    }
}

extern "C" void kernel_launch(void* const* d_in, const int* in_sizes, int n_in,
                              void* d_out, int out_size) {
    const float* regrs = (const float*)d_in[0];
    const float* ln_w  = (const float*)d_in[1];
    const float* ln_b  = (const float*)d_in[2];
    const float* W     = (const float*)d_in[3];
    float* out = (float*)d_out;

    int rows = in_sizes[0] / D_MODEL;                  // 32768
    int grid = (rows + 255) / 256;                     // 128

    cudaFuncSetAttribute(fsq_kernel,
                         cudaFuncAttributeMaxDynamicSharedMemorySize, SMEM_TOTAL);
    fsq_kernel<<<grid, TPB, SMEM_TOTAL>>>(regrs, ln_w, ln_b, W, out, rows);
}